// round 13
// baseline (speedup 1.0000x reference)
#include <cuda_runtime.h>
#include <cuda_bf16.h>
#include <cuda_fp16.h>
#include <stdint.h>

// ---------------- problem constants ----------------
#define B_    16384
#define DIN   768
#define HD0   512
#define HD1   256
#define HD2   128
#define NQ    4
#define KC    8192
#define EPS_  1e-6f

// VQ geometry (R11 proven): fp16 2-term A'=[hi|lo] 256 halves/row, B'=e_hi
// 128 row-blocks x 2 code-splits (64 tiles of 64 codes each)
#define TILE_N  64
#define TILES_PER_SPLIT 64
#define A_BLK_ELEMS (128 * 256)          // 64KB
#define B_TILE_ELEMS (TILE_N * 128)      // 16KB
#define SMEM_A_BYTES 65536
#define SMEM_B_BYTES 16384
#define SMEM_VQ (SMEM_A_BYTES + 2 * SMEM_B_BYTES)  // 98304
#define VQ_MARGIN 2e-3f

// MLP fp16 GEMM smem: A' 32KB + W double-buffer 2x16KB
#define SMEM_MLP 65536

// ---------------- scratch ----------------
__device__ float g_a[B_ * HD0];
__device__ float g_b[B_ * HD1];
__device__ float g_h[B_ * HD2];
__device__ float g_res[B_ * HD2];
__device__ float g_qsum[B_ * HD2];
__device__ float g_enorm[NQ * KC];
__device__ float g_vqrow[B_];
__device__ float g_rstd[DIN];
__device__ float g_p1[2048];
__device__ __half g_resA[B_ * 256];            // A' blocks hi|lo, pre-swizzled
__device__ __half g_cbB[NQ * KC * 128];        // B' tiles, pre-swizzled
__device__ __half g_Wh[2 * 557056];            // dec weights hi|lo swizzled (gain-folded)
__device__ unsigned long long g_pkey[2 * B_];
__device__ float g_psec[2 * B_];
__device__ unsigned g_done[128];               // last-CTA counters (self-resetting)

// dec weight tile bases (halves)
#define WBASE0 0
#define WBASE1 65536
#define WBASE2 327680

// ---------------- PTX helpers ----------------
__device__ __forceinline__ uint32_t smem_u32(const void* p) {
    uint32_t a;
    asm("{ .reg .u64 t; cvta.to.shared.u64 t, %1; cvt.u32.u64 %0, t; }" : "=r"(a) : "l"(p));
    return a;
}
#define CP_ASYNC16(dst, src) \
    asm volatile("cp.async.cg.shared.global [%0], [%1], 16;" :: "r"(dst), "l"(src))
#define CP_COMMIT() asm volatile("cp.async.commit_group;" ::: "memory")
#define CP_WAIT0()  asm volatile("cp.async.wait_group 0;" ::: "memory")
#define CP_WAIT1()  asm volatile("cp.async.wait_group 1;" ::: "memory")

__device__ __forceinline__ void ldsm_x4(uint32_t* r, uint32_t addr) {
    asm volatile("ldmatrix.sync.aligned.m8n8.x4.shared.b16 {%0,%1,%2,%3}, [%4];"
                 : "=r"(r[0]), "=r"(r[1]), "=r"(r[2]), "=r"(r[3]) : "r"(addr));
}
__device__ __forceinline__ void mma16816h(float* c, const uint32_t* a, const uint32_t* b) {
    asm volatile(
        "mma.sync.aligned.m16n8k16.row.col.f32.f16.f16.f32 "
        "{%0,%1,%2,%3}, {%4,%5,%6,%7}, {%8,%9}, {%0,%1,%2,%3};"
        : "+f"(c[0]), "+f"(c[1]), "+f"(c[2]), "+f"(c[3])
        : "r"(a[0]), "r"(a[1]), "r"(a[2]), "r"(a[3]), "r"(b[0]), "r"(b[1]));
}

__device__ __forceinline__ unsigned f2ord(float f) {
    unsigned u = __float_as_uint(f);
    return u ^ (((unsigned)((int)u >> 31)) | 0x80000000u);
}
__device__ __forceinline__ float ord2f(unsigned u) {
    u ^= (u & 0x80000000u) ? 0x80000000u : 0xFFFFFFFFu;
    return __uint_as_float(u);
}

// write residual element into swizzled fp16 hi/lo A' layout (512B rows)
__device__ __forceinline__ void writeA(int row, int k, float x) {
    __half hi = __float2half(x);
    __half lo = __float2half(x - __half2float(hi));
    int m = row & 127, rb = row >> 7;
    int q8 = k >> 3, b = (k & 7) * 2;
    int off_hi = m * 512 + ((q8 ^ (m & 7)) << 4) + b;
    int off_lo = m * 512 + (((16 + q8) ^ (m & 7)) << 4) + b;
    __half* base = g_resA + (size_t)rb * A_BLK_ELEMS;
    base[off_hi >> 1] = hi;
    base[off_lo >> 1] = lo;
}

// ---------------- small helpers ----------------
__device__ __forceinline__ float blockReduce256(float v) {
    __shared__ float red[32];
    int lane = threadIdx.x & 31, w = threadIdx.x >> 5;
#pragma unroll
    for (int o = 16; o > 0; o >>= 1) v += __shfl_down_sync(0xffffffffu, v, o);
    __syncthreads();
    if (lane == 0) red[w] = v;
    __syncthreads();
    if (threadIdx.x == 0) {
        float t = 0.0f;
        int nw = (blockDim.x + 31) >> 5;
        for (int i = 0; i < nw; i++) t += red[i];
        red[0] = t;
    }
    __syncthreads();
    return red[0];
}

__global__ void k_rstd(const float* __restrict__ stdv) {
    int i = blockIdx.x * blockDim.x + threadIdx.x;
    if (i < DIN) g_rstd[i] = 1.0f / stdv[i];
}

// ---------------- fp32 MLP GEMM (proven; NORM via rstd multiply) ----------------
template <bool RELU, bool NORM>
__global__ __launch_bounds__(256)
void k_gemm(const float* __restrict__ A, const float* __restrict__ W,
            const float* __restrict__ bias, float* __restrict__ C,
            int N, int K, const float* __restrict__ mean) {
    __shared__ float As[16][68];
    __shared__ float Ws[16][68];
    int m0 = blockIdx.y * 64, n0 = blockIdx.x * 64;
    int tid = threadIdx.x;
    int ty = tid >> 4, tx = tid & 15;
    int arow = tid >> 2, acol = (tid & 3) * 4;
    int wrow = tid >> 4, wcol = (tid & 15) * 4;

    float acc[4][4] = {};
    for (int k0 = 0; k0 < K; k0 += 16) {
        float4 av = *(const float4*)&A[(size_t)(m0 + arow) * K + k0 + acol];
        if (NORM) {
            int c = k0 + acol;
            av.x = (av.x - mean[c])     * g_rstd[c];
            av.y = (av.y - mean[c + 1]) * g_rstd[c + 1];
            av.z = (av.z - mean[c + 2]) * g_rstd[c + 2];
            av.w = (av.w - mean[c + 3]) * g_rstd[c + 3];
        }
        As[acol + 0][arow] = av.x;
        As[acol + 1][arow] = av.y;
        As[acol + 2][arow] = av.z;
        As[acol + 3][arow] = av.w;
        *(float4*)&Ws[wrow][wcol] =
            *(const float4*)&W[(size_t)(k0 + wrow) * N + n0 + wcol];
        __syncthreads();
#pragma unroll
        for (int k = 0; k < 16; k++) {
            float4 a4 = *(const float4*)&As[k][ty * 4];
            float4 w4 = *(const float4*)&Ws[k][tx * 4];
            float ar[4] = {a4.x, a4.y, a4.z, a4.w};
            float wr[4] = {w4.x, w4.y, w4.z, w4.w};
#pragma unroll
            for (int i = 0; i < 4; i++)
#pragma unroll
                for (int j = 0; j < 4; j++) acc[i][j] += ar[i] * wr[j];
        }
        __syncthreads();
    }
#pragma unroll
    for (int j = 0; j < 4; j++) {
        float bj = bias[n0 + tx * 4 + j];
#pragma unroll
        for (int i = 0; i < 4; i++) {
            float v = acc[i][j] + bj;
            if (RELU) v = fmaxf(v, 0.0f);
            C[(size_t)(m0 + ty * 4 + i) * N + n0 + tx * 4 + j] = v;
        }
    }
}

__global__ void k_rmsnorm(float* __restrict__ X, const float* __restrict__ g, int N) {
    int row = blockIdx.x;
    float* xr = X + (size_t)row * N;
    float s = 0.0f;
    for (int n = threadIdx.x; n < N; n += blockDim.x) {
        float v = xr[n];
        s += v * v;
    }
    s = blockReduce256(s);
    float scale = rsqrtf(s / (float)N + EPS_);
    for (int n = threadIdx.x; n < N; n += blockDim.x)
        xr[n] = xr[n] * scale * g[n];
}

// enc final rmsnorm fused with residual init
__global__ void k_rmsnorm_init(const float* __restrict__ g) {
    int row = blockIdx.x, d = threadIdx.x;  // 128 threads
    float v = g_h[(size_t)row * HD2 + d];
    __shared__ float s[128];
    s[d] = v * v;
    __syncthreads();
#pragma unroll
    for (int o = 64; o > 0; o >>= 1) {
        if (d < o) s[d] += s[d + o];
        __syncthreads();
    }
    float scale = rsqrtf(s[0] / (float)HD2 + EPS_);
    float hv = v * scale * g[d];
    g_res[(size_t)row * HD2 + d] = hv;
    writeA(row, d, hv);
}

__global__ void k_enorm(const float* __restrict__ cb) {
    int c = blockIdx.x * blockDim.x + threadIdx.x;
    if (c < NQ * KC) {
        const float4* p = (const float4*)(cb + (size_t)c * HD2);
        float s = 0.0f;
#pragma unroll 8
        for (int i = 0; i < HD2 / 4; i++) {
            float4 v = p[i];
            s += v.x * v.x + v.y * v.y + v.z * v.z + v.w * v.w;
        }
        g_enorm[c] = s;
    }
}

__global__ void k_prepB(const float* __restrict__ cb) {
    int idx = blockIdx.x * blockDim.x + threadIdx.x;
    if (idx >= NQ * KC * 128) return;
    int k = idx & 127;
    int qc = idx >> 7;
    int c = qc & (KC - 1), q = qc >> 13;
    __half v = __float2half(cb[(size_t)qc * HD2 + k]);
    int tile = c >> 6, n = c & 63;
    int byte = n * 256 + ((((k >> 3) ^ (n & 7))) << 4) + (k & 7) * 2;
    g_cbB[(size_t)q * (KC * 128) + tile * B_TILE_ELEMS + (byte >> 1)] = v;
}

// dec weight prep: W[K][N] (optionally * gain[k]) -> swizzled hi/lo tiles
__global__ void k_prepW(const float* __restrict__ W, const float* __restrict__ gain,
                        int K, int N, int base) {
    int idx = blockIdx.x * blockDim.x + threadIdx.x;
    if (idx >= K * N) return;
    int k = idx / N, n = idx - k * N;
    float v = W[idx];
    if (gain) v *= gain[k];
    __half hi = __float2half(v);
    __half lo = __float2half(v - __half2float(hi));
    int nt = n >> 6, nn = n & 63, kc = k >> 6, kk = k & 63;
    int ktiles = K >> 6;
    int toff = base + (nt * ktiles + kc) * 8192;
    int qhi = (kk >> 3) ^ (nn & 7);
    g_Wh[toff + ((nn * 256 + (qhi << 4) + (kk & 7) * 2) >> 1)] = hi;
    g_Wh[toff + ((nn * 256 + ((8 + qhi) << 4) + (kk & 7) * 2) >> 1)] = lo;
}

// ---------------- fp16 2-term MLP GEMM (dec path), optional fused input rmsnorm ----------------
template <bool RELU, bool SC>
__global__ __launch_bounds__(256)
void k_gemm_h(const float* __restrict__ A, const float* __restrict__ bias,
              float* __restrict__ C, int N, int K, int wbase) {
    extern __shared__ char smem[];
    __shared__ float ssqh[128];
    uint32_t sA = smem_u32(smem);
    uint32_t sW = sA + 32768;
    int tid = threadIdx.x, lid = tid & 31, wid = tid >> 5;
    int m0 = blockIdx.y * 128, n0 = blockIdx.x * 64;
    int wm = wid >> 1, wn = wid & 1;
    int tg = lid & 3, g = lid >> 2;
    int grp = lid >> 3, sub = lid & 7;
    int ktiles = K >> 6;
    const __half* Wcol = g_Wh + wbase + (size_t)blockIdx.x * ktiles * 8192;

    if (SC && tid < 128) ssqh[tid] = 0.0f;

    uint32_t aOff[2]; int aXor[2];
    int aG2 = grp >> 1;
#pragma unroll
    for (int mc = 0; mc < 2; mc++) {
        int row = wm * 32 + mc * 16 + (grp & 1) * 8 + sub;
        aOff[mc] = sA + row * 256;
        aXor[mc] = row & 7;
    }
    uint32_t bOff[2]; int bXor[2];
    int bK8b = grp & 1;
#pragma unroll
    for (int p = 0; p < 2; p++) {
        int n = wn * 32 + p * 16 + (grp >> 1) * 8 + sub;
        bOff[p] = n * 256;
        bXor[p] = n & 7;
    }

    {
        const char* gW = (const char*)Wcol;
        for (int i = tid; i < 1024; i += 256)
            CP_ASYNC16(sW + i * 16, gW + i * 16);
        CP_COMMIT();
    }

    float acc[2][4][4] = {};
    for (int t = 0; t < ktiles; t++) {
        float4 av[8];
#pragma unroll
        for (int j = 0; j < 8; j++) {
            int fidx = tid + j * 256;
            int m = fidx >> 4, f = fidx & 15;
            av[j] = *(const float4*)&A[(size_t)(m0 + m) * K + t * 64 + f * 4];
        }
        if (t + 1 < ktiles) {
            const char* gW = (const char*)(Wcol + (size_t)(t + 1) * 8192);
            uint32_t sWn = sW + ((t + 1) & 1) * 16384;
            for (int i = tid; i < 1024; i += 256)
                CP_ASYNC16(sWn + i * 16, gW + i * 16);
            CP_COMMIT();
        }
        __syncthreads();
#pragma unroll
        for (int j = 0; j < 8; j++) {
            int fidx = tid + j * 256;
            int m = fidx >> 4, f = fidx & 15;
            float4 v = av[j];
            if (SC) {
                float s = v.x * v.x + v.y * v.y + v.z * v.z + v.w * v.w;
                s += __shfl_xor_sync(0xffffffffu, s, 1);
                s += __shfl_xor_sync(0xffffffffu, s, 2);
                s += __shfl_xor_sync(0xffffffffu, s, 4);
                s += __shfl_xor_sync(0xffffffffu, s, 8);
                if (f == 0) ssqh[m] += s;
            }
            __half hx = __float2half(v.x), hy = __float2half(v.y);
            __half hz = __float2half(v.z), hw = __float2half(v.w);
            __half2 ph0 = __halves2half2(hx, hy), ph1 = __halves2half2(hz, hw);
            __half2 pl0 = __halves2half2(__float2half(v.x - __half2float(hx)),
                                         __float2half(v.y - __half2float(hy)));
            __half2 pl1 = __halves2half2(__float2half(v.z - __half2float(hz)),
                                         __float2half(v.w - __half2float(hw)));
            int q = f >> 1, bo = (f & 1) * 8;
            int offh = m * 256 + ((q ^ (m & 7)) << 4) + bo;
            int offl = m * 256 + (((8 + q) ^ (m & 7)) << 4) + bo;
            *(__half2*)(smem + offh) = ph0;
            *(__half2*)(smem + offh + 4) = ph1;
            *(__half2*)(smem + offl) = pl0;
            *(__half2*)(smem + offl + 4) = pl1;
        }
        if (t + 1 < ktiles) { CP_WAIT1(); } else { CP_WAIT0(); }
        __syncthreads();

        uint32_t sWt = sW + (t & 1) * 16384;
#pragma unroll
        for (int ks = 0; ks < 4; ks++) {
            uint32_t aH[2][4], aL[2][4], wH[2][4];
            int q8 = ks * 2 + aG2;
#pragma unroll
            for (int mc = 0; mc < 2; mc++) {
                ldsm_x4(aH[mc], aOff[mc] + ((q8 ^ aXor[mc]) << 4));
                ldsm_x4(aL[mc], aOff[mc] + (((8 + q8) ^ aXor[mc]) << 4));
            }
            int qb = ks * 2 + bK8b;
#pragma unroll
            for (int p = 0; p < 2; p++)
                ldsm_x4(wH[p], sWt + bOff[p] + ((qb ^ bXor[p]) << 4));
#pragma unroll
            for (int mc = 0; mc < 2; mc++)
#pragma unroll
                for (int c = 0; c < 4; c++) {
                    mma16816h(acc[mc][c], aH[mc], &wH[c >> 1][(c & 1) * 2]);
                    mma16816h(acc[mc][c], aL[mc], &wH[c >> 1][(c & 1) * 2]);
                }
        }
        __syncthreads();
    }

    float rk = 1.0f / (float)K;
#pragma unroll
    for (int mc = 0; mc < 2; mc++) {
        int lr0 = wm * 32 + mc * 16 + g;
        int lr1 = lr0 + 8;
        int r0 = m0 + lr0, r1 = m0 + lr1;
        float sc0 = 1.0f, sc1 = 1.0f;
        if (SC) {
            sc0 = rsqrtf(ssqh[lr0] * rk + EPS_);
            sc1 = rsqrtf(ssqh[lr1] * rk + EPS_);
        }
#pragma unroll
        for (int c = 0; c < 4; c++) {
            int cc = n0 + wn * 32 + c * 8 + tg * 2;
            float b0 = bias[cc], b1 = bias[cc + 1];
            float v0 = acc[mc][c][0], v1 = acc[mc][c][1];
            float v2 = acc[mc][c][2], v3 = acc[mc][c][3];
            if (SC) { v0 *= sc0; v1 *= sc0; v2 *= sc1; v3 *= sc1; }
            v0 += b0; v1 += b1; v2 += b0; v3 += b1;
            if (RELU) {
                v0 = fmaxf(v0, 0.0f); v1 = fmaxf(v1, 0.0f);
                v2 = fmaxf(v2, 0.0f); v3 = fmaxf(v3, 0.0f);
            }
            C[(size_t)r0 * N + cc] = v0;
            C[(size_t)r0 * N + cc + 1] = v1;
            C[(size_t)r1 * N + cc] = v2;
            C[(size_t)r1 * N + cc + 1] = v3;
        }
    }
}

// ---------------- fused VQ: score GEMM + argmin + last-CTA finish ----------------
__global__ __launch_bounds__(256, 2)
void k_vq_mma(const __half* __restrict__ Ablk,
              const __half* __restrict__ Bq,
              const float* __restrict__ en_q,
              const float* __restrict__ cb,
              float* __restrict__ out_ids, int q, int first) {
    extern __shared__ char smem[];
    uint32_t sA = smem_u32(smem);
    uint32_t sB0 = sA + SMEM_A_BYTES;
    __shared__ unsigned long long skey[2][128];
    __shared__ float ssec[2][128];
    __shared__ int sidx[128];
    __shared__ int s_fl[128];
    __shared__ unsigned s_nf, s_last;
    __shared__ float s_part[8];

    int tid = threadIdx.x, lid = tid & 31, wid = tid >> 5;
    int rb = blockIdx.x & 127, split = blockIdx.x >> 7;
    int wm = wid >> 1, wn = wid & 1;
    int tg = lid & 3, g = lid >> 2;
    int grp = lid >> 3, sub = lid & 7;

    const __half* Bs = Bq + (size_t)split * 4096 * 128;

    const char* gA = (const char*)(Ablk + (size_t)rb * A_BLK_ELEMS);
    for (int i = tid; i < 4096; i += 256)
        CP_ASYNC16(sA + i * 16, gA + i * 16);
    {
        const char* gB = (const char*)Bs;
        for (int i = tid; i < 1024; i += 256)
            CP_ASYNC16(sB0 + i * 16, gB + i * 16);
    }
    CP_COMMIT();

    uint32_t aOff[2]; int aXor[2];
    int aG2 = grp >> 1;
#pragma unroll
    for (int mc = 0; mc < 2; mc++) {
        int row = wm * 32 + mc * 16 + (grp & 1) * 8 + sub;
        aOff[mc] = sA + row * 512;
        aXor[mc] = row & 7;
    }
    uint32_t bOff[2]; int bXor[2];
    int bK8b = grp & 1;
#pragma unroll
    for (int p = 0; p < 2; p++) {
        int n = wn * 32 + p * 16 + (grp >> 1) * 8 + sub;
        bOff[p] = n * 256;
        bXor[p] = n & 7;
    }

    float bd[4] = {1e30f, 1e30f, 1e30f, 1e30f};
    float sd[4] = {1e30f, 1e30f, 1e30f, 1e30f};
    int bc[4] = {0, 0, 0, 0};

    for (int t = 0; t < TILES_PER_SPLIT; t++) {
        if (t + 1 < TILES_PER_SPLIT) {
            const char* gB = (const char*)(Bs + (size_t)(t + 1) * B_TILE_ELEMS);
            uint32_t sBn = sB0 + ((t + 1) & 1) * SMEM_B_BYTES;
            for (int i = tid; i < 1024; i += 256)
                CP_ASYNC16(sBn + i * 16, gB + i * 16);
            CP_COMMIT();
            CP_WAIT1();
        } else {
            CP_WAIT0();
        }
        __syncthreads();

        uint32_t sBt = sB0 + (t & 1) * SMEM_B_BYTES;
        float acc[2][4][4] = {};
#pragma unroll
        for (int ks = 0; ks < 8; ks++) {
            uint32_t bF[2][4];
            int qb = ks * 2 + bK8b;
#pragma unroll
            for (int p = 0; p < 2; p++)
                ldsm_x4(bF[p], sBt + bOff[p] + ((qb ^ bXor[p]) << 4));
            int q8 = ks * 2 + aG2;
            {
                uint32_t aH[2][4];
#pragma unroll
                for (int mc = 0; mc < 2; mc++)
                    ldsm_x4(aH[mc], aOff[mc] + ((q8 ^ aXor[mc]) << 4));
#pragma unroll
                for (int mc = 0; mc < 2; mc++)
#pragma unroll
                    for (int c = 0; c < 4; c++)
                        mma16816h(acc[mc][c], aH[mc], &bF[c >> 1][(c & 1) * 2]);
            }
            {
                uint32_t aL[2][4];
#pragma unroll
                for (int mc = 0; mc < 2; mc++)
                    ldsm_x4(aL[mc], aOff[mc] + (((16 + q8) ^ aXor[mc]) << 4));
#pragma unroll
                for (int mc = 0; mc < 2; mc++)
#pragma unroll
                    for (int c = 0; c < 4; c++)
                        mma16816h(acc[mc][c], aL[mc], &bF[c >> 1][(c & 1) * 2]);
            }
        }

        int colbase = split * 4096 + t * TILE_N + wn * 32;
#pragma unroll
        for (int c = 0; c < 4; c++) {
            int col0 = colbase + c * 8 + tg * 2;
            float e0 = __ldg(en_q + col0), e1 = __ldg(en_q + col0 + 1);
#pragma unroll
            for (int mc = 0; mc < 2; mc++) {
                float d0 = fmaf(-2.0f, acc[mc][c][0], e0);
                float d1 = fmaf(-2.0f, acc[mc][c][1], e1);
                float d2 = fmaf(-2.0f, acc[mc][c][2], e0);
                float d3 = fmaf(-2.0f, acc[mc][c][3], e1);
                int s0 = mc * 2, s1 = mc * 2 + 1;
                if (d0 < bd[s0]) { sd[s0] = bd[s0]; bd[s0] = d0; bc[s0] = col0; }
                else if (d0 < sd[s0]) sd[s0] = d0;
                if (d1 < bd[s0]) { sd[s0] = bd[s0]; bd[s0] = d1; bc[s0] = col0 + 1; }
                else if (d1 < sd[s0]) sd[s0] = d1;
                if (d2 < bd[s1]) { sd[s1] = bd[s1]; bd[s1] = d2; bc[s1] = col0; }
                else if (d2 < sd[s1]) sd[s1] = d2;
                if (d3 < bd[s1]) { sd[s1] = bd[s1]; bd[s1] = d3; bc[s1] = col0 + 1; }
                else if (d3 < sd[s1]) sd[s1] = d3;
            }
        }
        __syncthreads();
    }

#pragma unroll
    for (int s = 0; s < 4; s++) {
        unsigned long long key =
            ((unsigned long long)f2ord(bd[s]) << 32) | (unsigned)bc[s];
        float bf = bd[s], sf = sd[s];
#pragma unroll
        for (int off = 1; off <= 2; off <<= 1) {
            unsigned long long ok = __shfl_xor_sync(0xffffffffu, key, off);
            float os = __shfl_xor_sync(0xffffffffu, sf, off);
            float ob = ord2f((unsigned)(ok >> 32));
            sf = fminf(fmaxf(bf, ob), fminf(sf, os));
            bf = fminf(bf, ob);
            if (ok < key) key = ok;
        }
        if (tg == 0) {
            int row = wm * 32 + (s >> 1) * 16 + (s & 1) * 8 + g;
            skey[wn][row] = key;
            ssec[wn][row] = sf;
        }
    }
    __syncthreads();
    if (tid < 128) {
        unsigned long long k0 = skey[0][tid], k1 = skey[1][tid];
        float b0 = ord2f((unsigned)(k0 >> 32)), b1 = ord2f((unsigned)(k1 >> 32));
        float sec = fminf(fmaxf(b0, b1), fminf(ssec[0][tid], ssec[1][tid]));
        int row = rb * 128 + tid;
        g_pkey[split * B_ + row] = min(k0, k1);
        g_psec[split * B_ + row] = sec;
    }
    // ---- last-CTA finish (merge + rescan + update) ----
    __threadfence();
    __syncthreads();
    if (tid == 0) s_last = atomicAdd(&g_done[rb], 1u);
    __syncthreads();
    if (s_last != 1u) return;   // first arriver exits; second does the finish
    __threadfence();            // acquire peer's partials

    if (tid == 0) s_nf = 0;
    __syncthreads();
    if (tid < 128) {
        int row = rb * 128 + tid;
        unsigned long long k0 = g_pkey[row], k1 = g_pkey[B_ + row];
        float b0 = ord2f((unsigned)(k0 >> 32)), b1 = ord2f((unsigned)(k1 >> 32));
        float sec = fminf(fmaxf(b0, b1), fminf(g_psec[row], g_psec[B_ + row]));
        unsigned long long km = min(k0, k1);
        float best = ord2f((unsigned)(km >> 32));
        sidx[tid] = (int)(km & 0xFFFFFFFFu);
        if ((sec - best) < VQ_MARGIN) {
            int p = atomicAdd(&s_nf, 1u);
            s_fl[p] = tid;
        }
    }
    __syncthreads();
    int nf = (int)s_nf;

    // exact fp32 rescan for flagged rows (rare)
    float* s_r = ssec[1];
    unsigned long long* s_red = (unsigned long long*)&skey[0][0];  // 256 entries
    for (int i = 0; i < nf; i++) {
        int rowl = s_fl[i];
        if (tid < 128) s_r[tid] = g_res[(size_t)(rb * 128 + rowl) * HD2 + tid];
        __syncthreads();
        unsigned long long bk = ~0ULL;
        for (int c = tid; c < KC; c += 256) {
            const float4* e4 = (const float4*)(cb + (size_t)c * HD2);
            float dot = 0.0f;
#pragma unroll 8
            for (int u = 0; u < HD2 / 4; u++) {
                float4 v = e4[u];
                dot += s_r[4 * u] * v.x + s_r[4 * u + 1] * v.y +
                       s_r[4 * u + 2] * v.z + s_r[4 * u + 3] * v.w;
            }
            float d = en_q[c] - 2.0f * dot;
            unsigned long long key = ((unsigned long long)f2ord(d) << 32) | (unsigned)c;
            bk = min(bk, key);
        }
        s_red[tid] = bk;
        __syncthreads();
#pragma unroll
        for (int o = 128; o > 0; o >>= 1) {
            if (tid < o) s_red[tid] = min(s_red[tid], s_red[tid + o]);
            __syncthreads();
        }
        if (tid == 0) sidx[rowl] = (int)(s_red[0] & 0xFFFFFFFFu);
        __syncthreads();
    }

    // update: qsum/res/writeA + deterministic per-row sum of diff^2
    float* s_vq = ssec[0];
    for (int j = 0; j < 64; j++) {
        int rowl = (tid >> 7) + j * 2;     // threads 0-127 -> row 2j, 128-255 -> 2j+1
        int d = tid & 127;
        int row = rb * 128 + rowl;
        int idx = sidx[rowl];
        float e = cb[(size_t)idx * HD2 + d];
        size_t off = (size_t)row * HD2 + d;
        float rr = g_res[off];
        float diff = rr - e;
        if (first) g_qsum[off] = e;
        else g_qsum[off] += e;
        g_res[off] = diff;
        writeA(row, d, diff);
        float p = diff * diff;
#pragma unroll
        for (int o = 16; o > 0; o >>= 1) p += __shfl_down_sync(0xffffffffu, p, o);
        if (lid == 0) s_part[wid] = p;
        __syncthreads();
        if (tid == 0)
            s_vq[rowl] = s_part[0] + s_part[1] + s_part[2] + s_part[3];
        if (tid == 128)
            s_vq[rowl] = s_part[4] + s_part[5] + s_part[6] + s_part[7];
        __syncthreads();
    }
    if (tid < 128) {
        int row = rb * 128 + tid;
        if (first) g_vqrow[row] = s_vq[tid];
        else g_vqrow[row] += s_vq[tid];
        out_ids[(size_t)row * NQ + q] = (float)sidx[tid];
    }
    if (tid == 0) g_done[rb] = 0;   // self-reset for next launch
}

__global__ void k_recon_part(const float* __restrict__ recon,
                             const float* __restrict__ x,
                             const float* __restrict__ mean) {
    float sv = 0.0f;
    int n = B_ * DIN;
    for (int i = blockIdx.x * blockDim.x + threadIdx.x; i < n;
         i += gridDim.x * blockDim.x) {
        int c = i % DIN;
        float xn = (x[i] - mean[c]) * g_rstd[c];
        float d = recon[i] - xn;
        sv += d * d;
    }
    sv = blockReduce256(sv);
    if (threadIdx.x == 0) g_p1[blockIdx.x] = sv;
}

__global__ void k_final(float* __restrict__ out) {
    float s1 = 0.0f;
    for (int i = threadIdx.x; i < 2048; i += 256) s1 += g_p1[i];
    s1 = blockReduce256(s1);
    float s2 = 0.0f;
    for (int i = threadIdx.x; i < B_; i += 256) s2 += g_vqrow[i];
    s2 = blockReduce256(s2);
    if (threadIdx.x == 0) {
        out[0] = s1 / (float)((size_t)B_ * DIN);
        out[1] = 1.25f * s2 / (float)((size_t)B_ * HD2);
    }
}

// ---------------- launch ----------------
extern "C" void kernel_launch(void* const* d_in, const int* in_sizes, int n_in,
                              void* d_out, int out_size) {
    const float* x        = (const float*)d_in[0];
    const float* emb_mean = (const float*)d_in[1];
    const float* emb_std  = (const float*)d_in[2];
    const float* enc_w0   = (const float*)d_in[3];
    const float* enc_b0   = (const float*)d_in[4];
    const float* enc_g0   = (const float*)d_in[5];
    const float* enc_w1   = (const float*)d_in[6];
    const float* enc_b1   = (const float*)d_in[7];
    const float* enc_g1   = (const float*)d_in[8];
    const float* enc_w2   = (const float*)d_in[9];
    const float* enc_b2   = (const float*)d_in[10];
    const float* enc_g2   = (const float*)d_in[11];
    const float* cbs      = (const float*)d_in[12];
    const float* dec_w0   = (const float*)d_in[13];
    const float* dec_b0   = (const float*)d_in[14];
    const float* dec_g0   = (const float*)d_in[15];
    const float* dec_w1   = (const float*)d_in[16];
    const float* dec_b1   = (const float*)d_in[17];
    const float* dec_g1   = (const float*)d_in[18];
    const float* dec_w2   = (const float*)d_in[19];
    const float* dec_b2   = (const float*)d_in[20];

    float* out       = (float*)d_out;
    float* out_recon = out;
    float* out_ids   = out + (size_t)B_ * DIN;
    float* out_loss  = out_ids + (size_t)B_ * NQ;

    cudaFuncSetAttribute(k_vq_mma, cudaFuncAttributeMaxDynamicSharedMemorySize, SMEM_VQ);
    cudaFuncSetAttribute(k_gemm_h<true, false>, cudaFuncAttributeMaxDynamicSharedMemorySize, SMEM_MLP);
    cudaFuncSetAttribute(k_gemm_h<true, true>, cudaFuncAttributeMaxDynamicSharedMemorySize, SMEM_MLP);
    cudaFuncSetAttribute(k_gemm_h<false, true>, cudaFuncAttributeMaxDynamicSharedMemorySize, SMEM_MLP);

    float *p_a, *p_b, *p_h, *p_qsum, *p_en;
    void *pv_resA, *pv_cbB;
    cudaGetSymbolAddress((void**)&p_a, g_a);
    cudaGetSymbolAddress((void**)&p_b, g_b);
    cudaGetSymbolAddress((void**)&p_h, g_h);
    cudaGetSymbolAddress((void**)&p_qsum, g_qsum);
    cudaGetSymbolAddress((void**)&p_en, g_enorm);
    cudaGetSymbolAddress(&pv_resA, g_resA);
    cudaGetSymbolAddress(&pv_cbB, g_cbB);
    const __half* p_resA = (const __half*)pv_resA;
    const __half* p_cbB  = (const __half*)pv_cbB;

    // prep (independent of encoder)
    k_rstd<<<3, 256>>>(emb_std);
    k_enorm<<<(NQ * KC) / 256, 256>>>(cbs);
    k_prepB<<<(NQ * KC * 128) / 256, 256>>>(cbs);
    k_prepW<<<(HD2 * HD1 + 255) / 256, 256>>>(dec_w0, nullptr, HD2, HD1, WBASE0);
    k_prepW<<<(HD1 * HD0 + 255) / 256, 256>>>(dec_w1, dec_g0, HD1, HD0, WBASE1);
    k_prepW<<<(HD0 * DIN + 255) / 256, 256>>>(dec_w2, dec_g1, HD0, DIN, WBASE2);

    // encoder (fp32 — h must stay bit-compatible; enc0 fuses normalize via rstd)
    k_gemm<true, true><<<dim3(HD0 / 64, B_ / 64), 256>>>(x, enc_w0, enc_b0, p_a, HD0, DIN, emb_mean);
    k_rmsnorm<<<B_, 256>>>(p_a, enc_g0, HD0);
    k_gemm<true, false><<<dim3(HD1 / 64, B_ / 64), 256>>>(p_a, enc_w1, enc_b1, p_b, HD1, HD0, nullptr);
    k_rmsnorm<<<B_, 256>>>(p_b, enc_g1, HD1);
    k_gemm<true, false><<<dim3(HD2 / 64, B_ / 64), 256>>>(p_b, enc_w2, enc_b2, p_h, HD2, HD1, nullptr);
    k_rmsnorm_init<<<B_, 128>>>(enc_g2);

    // residual VQ (R11-proven 2-split, finish fused into last CTA per row-block)
    for (int q = 0; q < NQ; q++) {
        const float* cbq = cbs + (size_t)q * KC * HD2;
        k_vq_mma<<<256, 256, SMEM_VQ>>>(p_resA, p_cbB + (size_t)q * KC * 128,
                                        p_en + (size_t)q * KC, cbq, out_ids, q,
                                        q == 0 ? 1 : 0);
    }

    // decoder (fp16 2-term; dec1/dec2 fuse the input rmsnorm via ssq + folded gain)
    k_gemm_h<true, false><<<dim3(HD1 / 64, B_ / 128), 256, SMEM_MLP>>>(
        p_qsum, dec_b0, p_b, HD1, HD2, WBASE0);
    k_gemm_h<true, true><<<dim3(HD0 / 64, B_ / 128), 256, SMEM_MLP>>>(
        p_b, dec_b1, p_a, HD0, HD1, WBASE1);
    k_gemm_h<false, true><<<dim3(DIN / 64, B_ / 128), 256, SMEM_MLP>>>(
        p_a, dec_b2, out_recon, DIN, HD0, WBASE2);

    // losses
    k_recon_part<<<2048, 256>>>(out_recon, x, emb_mean);
    k_final<<<1, 256>>>(out_loss);
}

// round 14
// speedup vs baseline: 1.1400x; 1.1400x over previous
#include <cuda_runtime.h>
#include <cuda_bf16.h>
#include <cuda_fp16.h>
#include <stdint.h>

// ---------------- problem constants ----------------
#define B_    16384
#define DIN   768
#define HD0   512
#define HD1   256
#define HD2   128
#define NQ    4
#define KC    8192
#define EPS_  1e-6f

// VQ geometry (R11 proven): fp16 2-term A'=[hi|lo] 256 halves/row, B'=e_hi
#define TILE_N  64
#define TILES_PER_SPLIT 64
#define A_BLK_ELEMS (128 * 256)          // 64KB
#define B_TILE_ELEMS (TILE_N * 128)      // 16KB
#define SMEM_A_BYTES 65536
#define SMEM_B_BYTES 16384
#define SMEM_VQ (SMEM_A_BYTES + 2 * SMEM_B_BYTES)  // 98304
#define VQ_MARGIN 2e-3f

#define SMEM_MLP 65536

// ---------------- scratch ----------------
__device__ float g_a[B_ * HD0];
__device__ float g_b[B_ * HD1];
__device__ float g_h[B_ * HD2];
__device__ float g_res[B_ * HD2];
__device__ float g_qsum[B_ * HD2];
__device__ float g_enorm[NQ * KC];
__device__ float g_vqrow[B_];
__device__ float g_rstd[DIN];
__device__ float g_p1[2048];
__device__ float g_p2[64];
__device__ __half g_resA[B_ * 256];
__device__ __half g_cbB[NQ * KC * 128];
__device__ __half g_Wh[2 * 557056];
__device__ unsigned long long g_pkey[2 * B_];
__device__ float g_psec[2 * B_];

#define WBASE0 0
#define WBASE1 65536
#define WBASE2 327680

// ---------------- PTX helpers ----------------
__device__ __forceinline__ uint32_t smem_u32(const void* p) {
    uint32_t a;
    asm("{ .reg .u64 t; cvta.to.shared.u64 t, %1; cvt.u32.u64 %0, t; }" : "=r"(a) : "l"(p));
    return a;
}
#define CP_ASYNC16(dst, src) \
    asm volatile("cp.async.cg.shared.global [%0], [%1], 16;" :: "r"(dst), "l"(src))
#define CP_COMMIT() asm volatile("cp.async.commit_group;" ::: "memory")
#define CP_WAIT0()  asm volatile("cp.async.wait_group 0;" ::: "memory")
#define CP_WAIT1()  asm volatile("cp.async.wait_group 1;" ::: "memory")

__device__ __forceinline__ void ldsm_x4(uint32_t* r, uint32_t addr) {
    asm volatile("ldmatrix.sync.aligned.m8n8.x4.shared.b16 {%0,%1,%2,%3}, [%4];"
                 : "=r"(r[0]), "=r"(r[1]), "=r"(r[2]), "=r"(r[3]) : "r"(addr));
}
__device__ __forceinline__ void mma16816h(float* c, const uint32_t* a, const uint32_t* b) {
    asm volatile(
        "mma.sync.aligned.m16n8k16.row.col.f32.f16.f16.f32 "
        "{%0,%1,%2,%3}, {%4,%5,%6,%7}, {%8,%9}, {%0,%1,%2,%3};"
        : "+f"(c[0]), "+f"(c[1]), "+f"(c[2]), "+f"(c[3])
        : "r"(a[0]), "r"(a[1]), "r"(a[2]), "r"(a[3]), "r"(b[0]), "r"(b[1]));
}

__device__ __forceinline__ unsigned f2ord(float f) {
    unsigned u = __float_as_uint(f);
    return u ^ (((unsigned)((int)u >> 31)) | 0x80000000u);
}
__device__ __forceinline__ float ord2f(unsigned u) {
    u ^= (u & 0x80000000u) ? 0x80000000u : 0xFFFFFFFFu;
    return __uint_as_float(u);
}

// write residual element into swizzled fp16 hi/lo A' layout (512B rows)
__device__ __forceinline__ void writeA(int row, int k, float x) {
    __half hi = __float2half(x);
    __half lo = __float2half(x - __half2float(hi));
    int m = row & 127, rb = row >> 7;
    int q8 = k >> 3, b = (k & 7) * 2;
    int off_hi = m * 512 + ((q8 ^ (m & 7)) << 4) + b;
    int off_lo = m * 512 + (((16 + q8) ^ (m & 7)) << 4) + b;
    __half* base = g_resA + (size_t)rb * A_BLK_ELEMS;
    base[off_hi >> 1] = hi;
    base[off_lo >> 1] = lo;
}

// ---------------- small helpers ----------------
__device__ __forceinline__ float blockReduce256(float v) {
    __shared__ float red[32];
    int lane = threadIdx.x & 31, w = threadIdx.x >> 5;
#pragma unroll
    for (int o = 16; o > 0; o >>= 1) v += __shfl_down_sync(0xffffffffu, v, o);
    __syncthreads();
    if (lane == 0) red[w] = v;
    __syncthreads();
    if (threadIdx.x == 0) {
        float t = 0.0f;
        int nw = (blockDim.x + 31) >> 5;
        for (int i = 0; i < nw; i++) t += red[i];
        red[0] = t;
    }
    __syncthreads();
    return red[0];
}

// ---------------- merged prep: rstd + enorm + prepB in one grid-stride kernel ----------------
#define PREPB_N (NQ * KC * 128)          // 4194304
#define ENORM_N (NQ * KC)                // 32768
__global__ void k_prep_all(const float* __restrict__ cb,
                           const float* __restrict__ stdv) {
    for (int idx = blockIdx.x * blockDim.x + threadIdx.x;
         idx < PREPB_N + ENORM_N + DIN; idx += gridDim.x * blockDim.x) {
        if (idx < PREPB_N) {
            int k = idx & 127;
            int qc = idx >> 7;
            int c = qc & (KC - 1), q = qc >> 13;
            __half v = __float2half(cb[(size_t)qc * HD2 + k]);
            int tile = c >> 6, n = c & 63;
            int byte = n * 256 + ((((k >> 3) ^ (n & 7))) << 4) + (k & 7) * 2;
            g_cbB[(size_t)q * (KC * 128) + tile * B_TILE_ELEMS + (byte >> 1)] = v;
        } else if (idx < PREPB_N + ENORM_N) {
            int c = idx - PREPB_N;
            const float4* p = (const float4*)(cb + (size_t)c * HD2);
            float s = 0.0f;
#pragma unroll 8
            for (int i = 0; i < HD2 / 4; i++) {
                float4 v = p[i];
                s += v.x * v.x + v.y * v.y + v.z * v.z + v.w * v.w;
            }
            g_enorm[c] = s;
        } else {
            int c = idx - PREPB_N - ENORM_N;
            g_rstd[c] = 1.0f / stdv[c];
        }
    }
}

// merged dec-weight prep (3 segments, gain-folded) — same math as k_prepW
__device__ __forceinline__ void prepW_one(const float* W, const float* gain,
                                          int K, int N, int base, int idx) {
    int k = idx / N, n = idx - k * N;
    float v = W[idx];
    if (gain) v *= gain[k];
    __half hi = __float2half(v);
    __half lo = __float2half(v - __half2float(hi));
    int nt = n >> 6, nn = n & 63, kc = k >> 6, kk = k & 63;
    int ktiles = K >> 6;
    int toff = base + (nt * ktiles + kc) * 8192;
    int qhi = (kk >> 3) ^ (nn & 7);
    g_Wh[toff + ((nn * 256 + (qhi << 4) + (kk & 7) * 2) >> 1)] = hi;
    g_Wh[toff + ((nn * 256 + ((8 + qhi) << 4) + (kk & 7) * 2) >> 1)] = lo;
}
#define W0N (HD2 * HD1)   // 32768
#define W1N (HD1 * HD0)   // 131072
#define W2N (HD0 * DIN)   // 393216
__global__ void k_prepW_all(const float* __restrict__ w0,
                            const float* __restrict__ w1, const float* __restrict__ g0,
                            const float* __restrict__ w2, const float* __restrict__ g1) {
    for (int idx = blockIdx.x * blockDim.x + threadIdx.x;
         idx < W0N + W1N + W2N; idx += gridDim.x * blockDim.x) {
        if (idx < W0N)            prepW_one(w0, nullptr, HD2, HD1, WBASE0, idx);
        else if (idx < W0N + W1N) prepW_one(w1, g0, HD1, HD0, WBASE1, idx - W0N);
        else                      prepW_one(w2, g1, HD0, DIN, WBASE2, idx - W0N - W1N);
    }
}

// ---------------- fp32 MLP GEMM (proven; NORM via rstd multiply) ----------------
template <bool RELU, bool NORM>
__global__ __launch_bounds__(256)
void k_gemm(const float* __restrict__ A, const float* __restrict__ W,
            const float* __restrict__ bias, float* __restrict__ C,
            int N, int K, const float* __restrict__ mean) {
    __shared__ float As[16][68];
    __shared__ float Ws[16][68];
    int m0 = blockIdx.y * 64, n0 = blockIdx.x * 64;
    int tid = threadIdx.x;
    int ty = tid >> 4, tx = tid & 15;
    int arow = tid >> 2, acol = (tid & 3) * 4;
    int wrow = tid >> 4, wcol = (tid & 15) * 4;

    float acc[4][4] = {};
    for (int k0 = 0; k0 < K; k0 += 16) {
        float4 av = *(const float4*)&A[(size_t)(m0 + arow) * K + k0 + acol];
        if (NORM) {
            int c = k0 + acol;
            av.x = (av.x - mean[c])     * g_rstd[c];
            av.y = (av.y - mean[c + 1]) * g_rstd[c + 1];
            av.z = (av.z - mean[c + 2]) * g_rstd[c + 2];
            av.w = (av.w - mean[c + 3]) * g_rstd[c + 3];
        }
        As[acol + 0][arow] = av.x;
        As[acol + 1][arow] = av.y;
        As[acol + 2][arow] = av.z;
        As[acol + 3][arow] = av.w;
        *(float4*)&Ws[wrow][wcol] =
            *(const float4*)&W[(size_t)(k0 + wrow) * N + n0 + wcol];
        __syncthreads();
#pragma unroll
        for (int k = 0; k < 16; k++) {
            float4 a4 = *(const float4*)&As[k][ty * 4];
            float4 w4 = *(const float4*)&Ws[k][tx * 4];
            float ar[4] = {a4.x, a4.y, a4.z, a4.w};
            float wr[4] = {w4.x, w4.y, w4.z, w4.w};
#pragma unroll
            for (int i = 0; i < 4; i++)
#pragma unroll
                for (int j = 0; j < 4; j++) acc[i][j] += ar[i] * wr[j];
        }
        __syncthreads();
    }
#pragma unroll
    for (int j = 0; j < 4; j++) {
        float bj = bias[n0 + tx * 4 + j];
#pragma unroll
        for (int i = 0; i < 4; i++) {
            float v = acc[i][j] + bj;
            if (RELU) v = fmaxf(v, 0.0f);
            C[(size_t)(m0 + ty * 4 + i) * N + n0 + tx * 4 + j] = v;
        }
    }
}

__global__ void k_rmsnorm(float* __restrict__ X, const float* __restrict__ g, int N) {
    int row = blockIdx.x;
    float* xr = X + (size_t)row * N;
    float s = 0.0f;
    for (int n = threadIdx.x; n < N; n += blockDim.x) {
        float v = xr[n];
        s += v * v;
    }
    s = blockReduce256(s);
    float scale = rsqrtf(s / (float)N + EPS_);
    for (int n = threadIdx.x; n < N; n += blockDim.x)
        xr[n] = xr[n] * scale * g[n];
}

// enc final rmsnorm fused with residual init
__global__ void k_rmsnorm_init(const float* __restrict__ g) {
    int row = blockIdx.x, d = threadIdx.x;
    float v = g_h[(size_t)row * HD2 + d];
    __shared__ float s[128];
    s[d] = v * v;
    __syncthreads();
#pragma unroll
    for (int o = 64; o > 0; o >>= 1) {
        if (d < o) s[d] += s[d + o];
        __syncthreads();
    }
    float scale = rsqrtf(s[0] / (float)HD2 + EPS_);
    float hv = v * scale * g[d];
    g_res[(size_t)row * HD2 + d] = hv;
    writeA(row, d, hv);
}

// ---------------- fp16 2-term MLP GEMM (dec path), optional fused input rmsnorm ----------------
template <bool RELU, bool SC>
__global__ __launch_bounds__(256)
void k_gemm_h(const float* __restrict__ A, const float* __restrict__ bias,
              float* __restrict__ C, int N, int K, int wbase) {
    extern __shared__ char smem[];
    __shared__ float ssqh[128];
    uint32_t sA = smem_u32(smem);
    uint32_t sW = sA + 32768;
    int tid = threadIdx.x, lid = tid & 31, wid = tid >> 5;
    int m0 = blockIdx.y * 128, n0 = blockIdx.x * 64;
    int wm = wid >> 1, wn = wid & 1;
    int tg = lid & 3, g = lid >> 2;
    int grp = lid >> 3, sub = lid & 7;
    int ktiles = K >> 6;
    const __half* Wcol = g_Wh + wbase + (size_t)blockIdx.x * ktiles * 8192;

    if (SC && tid < 128) ssqh[tid] = 0.0f;

    uint32_t aOff[2]; int aXor[2];
    int aG2 = grp >> 1;
#pragma unroll
    for (int mc = 0; mc < 2; mc++) {
        int row = wm * 32 + mc * 16 + (grp & 1) * 8 + sub;
        aOff[mc] = sA + row * 256;
        aXor[mc] = row & 7;
    }
    uint32_t bOff[2]; int bXor[2];
    int bK8b = grp & 1;
#pragma unroll
    for (int p = 0; p < 2; p++) {
        int n = wn * 32 + p * 16 + (grp >> 1) * 8 + sub;
        bOff[p] = n * 256;
        bXor[p] = n & 7;
    }

    {
        const char* gW = (const char*)Wcol;
        for (int i = tid; i < 1024; i += 256)
            CP_ASYNC16(sW + i * 16, gW + i * 16);
        CP_COMMIT();
    }

    float acc[2][4][4] = {};
    for (int t = 0; t < ktiles; t++) {
        float4 av[8];
#pragma unroll
        for (int j = 0; j < 8; j++) {
            int fidx = tid + j * 256;
            int m = fidx >> 4, f = fidx & 15;
            av[j] = *(const float4*)&A[(size_t)(m0 + m) * K + t * 64 + f * 4];
        }
        if (t + 1 < ktiles) {
            const char* gW = (const char*)(Wcol + (size_t)(t + 1) * 8192);
            uint32_t sWn = sW + ((t + 1) & 1) * 16384;
            for (int i = tid; i < 1024; i += 256)
                CP_ASYNC16(sWn + i * 16, gW + i * 16);
            CP_COMMIT();
        }
        __syncthreads();
#pragma unroll
        for (int j = 0; j < 8; j++) {
            int fidx = tid + j * 256;
            int m = fidx >> 4, f = fidx & 15;
            float4 v = av[j];
            if (SC) {
                float s = v.x * v.x + v.y * v.y + v.z * v.z + v.w * v.w;
                s += __shfl_xor_sync(0xffffffffu, s, 1);
                s += __shfl_xor_sync(0xffffffffu, s, 2);
                s += __shfl_xor_sync(0xffffffffu, s, 4);
                s += __shfl_xor_sync(0xffffffffu, s, 8);
                if (f == 0) ssqh[m] += s;
            }
            __half hx = __float2half(v.x), hy = __float2half(v.y);
            __half hz = __float2half(v.z), hw = __float2half(v.w);
            __half2 ph0 = __halves2half2(hx, hy), ph1 = __halves2half2(hz, hw);
            __half2 pl0 = __halves2half2(__float2half(v.x - __half2float(hx)),
                                         __float2half(v.y - __half2float(hy)));
            __half2 pl1 = __halves2half2(__float2half(v.z - __half2float(hz)),
                                         __float2half(v.w - __half2float(hw)));
            int q = f >> 1, bo = (f & 1) * 8;
            int offh = m * 256 + ((q ^ (m & 7)) << 4) + bo;
            int offl = m * 256 + (((8 + q) ^ (m & 7)) << 4) + bo;
            *(__half2*)(smem + offh) = ph0;
            *(__half2*)(smem + offh + 4) = ph1;
            *(__half2*)(smem + offl) = pl0;
            *(__half2*)(smem + offl + 4) = pl1;
        }
        if (t + 1 < ktiles) { CP_WAIT1(); } else { CP_WAIT0(); }
        __syncthreads();

        uint32_t sWt = sW + (t & 1) * 16384;
#pragma unroll
        for (int ks = 0; ks < 4; ks++) {
            uint32_t aH[2][4], aL[2][4], wH[2][4];
            int q8 = ks * 2 + aG2;
#pragma unroll
            for (int mc = 0; mc < 2; mc++) {
                ldsm_x4(aH[mc], aOff[mc] + ((q8 ^ aXor[mc]) << 4));
                ldsm_x4(aL[mc], aOff[mc] + (((8 + q8) ^ aXor[mc]) << 4));
            }
            int qb = ks * 2 + bK8b;
#pragma unroll
            for (int p = 0; p < 2; p++)
                ldsm_x4(wH[p], sWt + bOff[p] + ((qb ^ bXor[p]) << 4));
#pragma unroll
            for (int mc = 0; mc < 2; mc++)
#pragma unroll
                for (int c = 0; c < 4; c++) {
                    mma16816h(acc[mc][c], aH[mc], &wH[c >> 1][(c & 1) * 2]);
                    mma16816h(acc[mc][c], aL[mc], &wH[c >> 1][(c & 1) * 2]);
                }
        }
        __syncthreads();
    }

    float rk = 1.0f / (float)K;
#pragma unroll
    for (int mc = 0; mc < 2; mc++) {
        int lr0 = wm * 32 + mc * 16 + g;
        int lr1 = lr0 + 8;
        int r0 = m0 + lr0, r1 = m0 + lr1;
        float sc0 = 1.0f, sc1 = 1.0f;
        if (SC) {
            sc0 = rsqrtf(ssqh[lr0] * rk + EPS_);
            sc1 = rsqrtf(ssqh[lr1] * rk + EPS_);
        }
#pragma unroll
        for (int c = 0; c < 4; c++) {
            int cc = n0 + wn * 32 + c * 8 + tg * 2;
            float b0 = bias[cc], b1 = bias[cc + 1];
            float v0 = acc[mc][c][0], v1 = acc[mc][c][1];
            float v2 = acc[mc][c][2], v3 = acc[mc][c][3];
            if (SC) { v0 *= sc0; v1 *= sc0; v2 *= sc1; v3 *= sc1; }
            v0 += b0; v1 += b1; v2 += b0; v3 += b1;
            if (RELU) {
                v0 = fmaxf(v0, 0.0f); v1 = fmaxf(v1, 0.0f);
                v2 = fmaxf(v2, 0.0f); v3 = fmaxf(v3, 0.0f);
            }
            C[(size_t)r0 * N + cc] = v0;
            C[(size_t)r0 * N + cc + 1] = v1;
            C[(size_t)r1 * N + cc] = v2;
            C[(size_t)r1 * N + cc + 1] = v3;
        }
    }
}

// ---------------- fused VQ score GEMM + argmin (R11-proven, 2-way split) ----------------
__global__ __launch_bounds__(256, 2)
void k_vq_mma(const __half* __restrict__ Ablk,
              const __half* __restrict__ Bq,
              const float* __restrict__ en_q) {
    extern __shared__ char smem[];
    uint32_t sA = smem_u32(smem);
    uint32_t sB0 = sA + SMEM_A_BYTES;
    __shared__ unsigned long long skey[2][128];
    __shared__ float ssec[2][128];

    int tid = threadIdx.x, lid = tid & 31, wid = tid >> 5;
    int rb = blockIdx.x & 127, split = blockIdx.x >> 7;
    int wm = wid >> 1, wn = wid & 1;
    int tg = lid & 3, g = lid >> 2;
    int grp = lid >> 3, sub = lid & 7;

    const __half* Bs = Bq + (size_t)split * 4096 * 128;

    const char* gA = (const char*)(Ablk + (size_t)rb * A_BLK_ELEMS);
    for (int i = tid; i < 4096; i += 256)
        CP_ASYNC16(sA + i * 16, gA + i * 16);
    {
        const char* gB = (const char*)Bs;
        for (int i = tid; i < 1024; i += 256)
            CP_ASYNC16(sB0 + i * 16, gB + i * 16);
    }
    CP_COMMIT();

    uint32_t aOff[2]; int aXor[2];
    int aG2 = grp >> 1;
#pragma unroll
    for (int mc = 0; mc < 2; mc++) {
        int row = wm * 32 + mc * 16 + (grp & 1) * 8 + sub;
        aOff[mc] = sA + row * 512;
        aXor[mc] = row & 7;
    }
    uint32_t bOff[2]; int bXor[2];
    int bK8b = grp & 1;
#pragma unroll
    for (int p = 0; p < 2; p++) {
        int n = wn * 32 + p * 16 + (grp >> 1) * 8 + sub;
        bOff[p] = n * 256;
        bXor[p] = n & 7;
    }

    float bd[4] = {1e30f, 1e30f, 1e30f, 1e30f};
    float sd[4] = {1e30f, 1e30f, 1e30f, 1e30f};
    int bc[4] = {0, 0, 0, 0};

    for (int t = 0; t < TILES_PER_SPLIT; t++) {
        if (t + 1 < TILES_PER_SPLIT) {
            const char* gB = (const char*)(Bs + (size_t)(t + 1) * B_TILE_ELEMS);
            uint32_t sBn = sB0 + ((t + 1) & 1) * SMEM_B_BYTES;
            for (int i = tid; i < 1024; i += 256)
                CP_ASYNC16(sBn + i * 16, gB + i * 16);
            CP_COMMIT();
            CP_WAIT1();
        } else {
            CP_WAIT0();
        }
        __syncthreads();

        uint32_t sBt = sB0 + (t & 1) * SMEM_B_BYTES;
        float acc[2][4][4] = {};
#pragma unroll
        for (int ks = 0; ks < 8; ks++) {
            uint32_t bF[2][4];
            int qb = ks * 2 + bK8b;
#pragma unroll
            for (int p = 0; p < 2; p++)
                ldsm_x4(bF[p], sBt + bOff[p] + ((qb ^ bXor[p]) << 4));
            int q8 = ks * 2 + aG2;
            {
                uint32_t aH[2][4];
#pragma unroll
                for (int mc = 0; mc < 2; mc++)
                    ldsm_x4(aH[mc], aOff[mc] + ((q8 ^ aXor[mc]) << 4));
#pragma unroll
                for (int mc = 0; mc < 2; mc++)
#pragma unroll
                    for (int c = 0; c < 4; c++)
                        mma16816h(acc[mc][c], aH[mc], &bF[c >> 1][(c & 1) * 2]);
            }
            {
                uint32_t aL[2][4];
#pragma unroll
                for (int mc = 0; mc < 2; mc++)
                    ldsm_x4(aL[mc], aOff[mc] + (((16 + q8) ^ aXor[mc]) << 4));
#pragma unroll
                for (int mc = 0; mc < 2; mc++)
#pragma unroll
                    for (int c = 0; c < 4; c++)
                        mma16816h(acc[mc][c], aL[mc], &bF[c >> 1][(c & 1) * 2]);
            }
        }

        int colbase = split * 4096 + t * TILE_N + wn * 32;
#pragma unroll
        for (int c = 0; c < 4; c++) {
            int col0 = colbase + c * 8 + tg * 2;
            float e0 = __ldg(en_q + col0), e1 = __ldg(en_q + col0 + 1);
#pragma unroll
            for (int mc = 0; mc < 2; mc++) {
                float d0 = fmaf(-2.0f, acc[mc][c][0], e0);
                float d1 = fmaf(-2.0f, acc[mc][c][1], e1);
                float d2 = fmaf(-2.0f, acc[mc][c][2], e0);
                float d3 = fmaf(-2.0f, acc[mc][c][3], e1);
                int s0 = mc * 2, s1 = mc * 2 + 1;
                if (d0 < bd[s0]) { sd[s0] = bd[s0]; bd[s0] = d0; bc[s0] = col0; }
                else if (d0 < sd[s0]) sd[s0] = d0;
                if (d1 < bd[s0]) { sd[s0] = bd[s0]; bd[s0] = d1; bc[s0] = col0 + 1; }
                else if (d1 < sd[s0]) sd[s0] = d1;
                if (d2 < bd[s1]) { sd[s1] = bd[s1]; bd[s1] = d2; bc[s1] = col0; }
                else if (d2 < sd[s1]) sd[s1] = d2;
                if (d3 < bd[s1]) { sd[s1] = bd[s1]; bd[s1] = d3; bc[s1] = col0 + 1; }
                else if (d3 < sd[s1]) sd[s1] = d3;
            }
        }
        __syncthreads();
    }

#pragma unroll
    for (int s = 0; s < 4; s++) {
        unsigned long long key =
            ((unsigned long long)f2ord(bd[s]) << 32) | (unsigned)bc[s];
        float bf = bd[s], sf = sd[s];
#pragma unroll
        for (int off = 1; off <= 2; off <<= 1) {
            unsigned long long ok = __shfl_xor_sync(0xffffffffu, key, off);
            float os = __shfl_xor_sync(0xffffffffu, sf, off);
            float ob = ord2f((unsigned)(ok >> 32));
            sf = fminf(fmaxf(bf, ob), fminf(sf, os));
            bf = fminf(bf, ob);
            if (ok < key) key = ok;
        }
        if (tg == 0) {
            int row = wm * 32 + (s >> 1) * 16 + (s & 1) * 8 + g;
            skey[wn][row] = key;
            ssec[wn][row] = sf;
        }
    }
    __syncthreads();
    if (tid < 128) {
        unsigned long long k0 = skey[0][tid], k1 = skey[1][tid];
        float b0 = ord2f((unsigned)(k0 >> 32)), b1 = ord2f((unsigned)(k1 >> 32));
        float sec = fminf(fmaxf(b0, b1), fminf(ssec[0][tid], ssec[1][tid]));
        int row = rb * 128 + tid;
        g_pkey[split * B_ + row] = min(k0, k1);
        g_psec[split * B_ + row] = sec;
    }
}

// fused: 2-way split merge + (rare) exact rescan + gather/update/next-A' (proven)
__global__ void k_vq_finish(const float* __restrict__ cb,
                            const float* __restrict__ en,
                            float* __restrict__ out_ids, int q, int first) {
    int row = blockIdx.x, t = threadIdx.x;
    __shared__ float r[HD2];
    __shared__ unsigned long long red[128];
    __shared__ float s[128];

    unsigned long long k0 = g_pkey[row], k1 = g_pkey[B_ + row];
    float b0 = ord2f((unsigned)(k0 >> 32)), b1 = ord2f((unsigned)(k1 >> 32));
    float sec = fminf(fmaxf(b0, b1), fminf(g_psec[row], g_psec[B_ + row]));
    unsigned long long km = min(k0, k1);
    float best = ord2f((unsigned)(km >> 32));
    int idx;
    if ((sec - best) >= VQ_MARGIN) {
        idx = (int)(km & 0xFFFFFFFFu);
    } else {
        r[t] = g_res[(size_t)row * HD2 + t];
        __syncthreads();
        unsigned long long bk = ~0ULL;
        for (int c = t; c < KC; c += 128) {
            const float4* e4 = (const float4*)(cb + (size_t)c * HD2);
            float dot = 0.0f;
#pragma unroll 8
            for (int i = 0; i < HD2 / 4; i++) {
                float4 v = e4[i];
                dot += r[4 * i] * v.x + r[4 * i + 1] * v.y +
                       r[4 * i + 2] * v.z + r[4 * i + 3] * v.w;
            }
            float d = en[c] - 2.0f * dot;
            unsigned long long key = ((unsigned long long)f2ord(d) << 32) | (unsigned)c;
            bk = min(bk, key);
        }
        red[t] = bk;
        __syncthreads();
#pragma unroll
        for (int o = 64; o > 0; o >>= 1) {
            if (t < o) red[t] = min(red[t], red[t + o]);
            __syncthreads();
        }
        idx = (int)(red[0] & 0xFFFFFFFFu);
    }

    float e = cb[(size_t)idx * HD2 + t];
    size_t off = (size_t)row * HD2 + t;
    float rr = g_res[off];
    float diff = rr - e;
    if (first) g_qsum[off] = e;
    else g_qsum[off] += e;
    g_res[off] = diff;
    writeA(row, t, diff);

    s[t] = diff * diff;
    __syncthreads();
#pragma unroll
    for (int o = 64; o > 0; o >>= 1) {
        if (t < o) s[t] += s[t + o];
        __syncthreads();
    }
    if (t == 0) {
        if (first) g_vqrow[row] = s[0];
        else g_vqrow[row] += s[0];
        out_ids[(size_t)row * NQ + q] = (float)idx;
    }
}

__global__ void k_recon_part(const float* __restrict__ recon,
                             const float* __restrict__ x,
                             const float* __restrict__ mean) {
    float sv = 0.0f;
    int n = B_ * DIN;
    for (int i = blockIdx.x * blockDim.x + threadIdx.x; i < n;
         i += gridDim.x * blockDim.x) {
        int c = i % DIN;
        float xn = (x[i] - mean[c]) * g_rstd[c];
        float d = recon[i] - xn;
        sv += d * d;
    }
    sv = blockReduce256(sv);
    if (threadIdx.x == 0) g_p1[blockIdx.x] = sv;
}

__global__ void k_vq_part() {
    float sv = 0.0f;
    for (int i = blockIdx.x * blockDim.x + threadIdx.x; i < B_;
         i += gridDim.x * blockDim.x)
        sv += g_vqrow[i];
    sv = blockReduce256(sv);
    if (threadIdx.x == 0) g_p2[blockIdx.x] = sv;
}

__global__ void k_final(float* __restrict__ out) {
    float s1 = 0.0f;
    for (int i = threadIdx.x; i < 2048; i += 256) s1 += g_p1[i];
    s1 = blockReduce256(s1);
    float s2 = 0.0f;
    for (int i = threadIdx.x; i < 64; i += 256) s2 += g_p2[i];
    s2 = blockReduce256(s2);
    if (threadIdx.x == 0) {
        out[0] = s1 / (float)((size_t)B_ * DIN);
        out[1] = 1.25f * s2 / (float)((size_t)B_ * HD2);
    }
}

// ---------------- launch ----------------
extern "C" void kernel_launch(void* const* d_in, const int* in_sizes, int n_in,
                              void* d_out, int out_size) {
    const float* x        = (const float*)d_in[0];
    const float* emb_mean = (const float*)d_in[1];
    const float* emb_std  = (const float*)d_in[2];
    const float* enc_w0   = (const float*)d_in[3];
    const float* enc_b0   = (const float*)d_in[4];
    const float* enc_g0   = (const float*)d_in[5];
    const float* enc_w1   = (const float*)d_in[6];
    const float* enc_b1   = (const float*)d_in[7];
    const float* enc_g1   = (const float*)d_in[8];
    const float* enc_w2   = (const float*)d_in[9];
    const float* enc_b2   = (const float*)d_in[10];
    const float* enc_g2   = (const float*)d_in[11];
    const float* cbs      = (const float*)d_in[12];
    const float* dec_w0   = (const float*)d_in[13];
    const float* dec_b0   = (const float*)d_in[14];
    const float* dec_g0   = (const float*)d_in[15];
    const float* dec_w1   = (const float*)d_in[16];
    const float* dec_b1   = (const float*)d_in[17];
    const float* dec_g1   = (const float*)d_in[18];
    const float* dec_w2   = (const float*)d_in[19];
    const float* dec_b2   = (const float*)d_in[20];

    float* out       = (float*)d_out;
    float* out_recon = out;
    float* out_ids   = out + (size_t)B_ * DIN;
    float* out_loss  = out_ids + (size_t)B_ * NQ;

    cudaFuncSetAttribute(k_vq_mma, cudaFuncAttributeMaxDynamicSharedMemorySize, SMEM_VQ);
    cudaFuncSetAttribute(k_gemm_h<true, false>, cudaFuncAttributeMaxDynamicSharedMemorySize, SMEM_MLP);
    cudaFuncSetAttribute(k_gemm_h<true, true>, cudaFuncAttributeMaxDynamicSharedMemorySize, SMEM_MLP);
    cudaFuncSetAttribute(k_gemm_h<false, true>, cudaFuncAttributeMaxDynamicSharedMemorySize, SMEM_MLP);

    float *p_a, *p_b, *p_h, *p_qsum, *p_en;
    void *pv_resA, *pv_cbB;
    cudaGetSymbolAddress((void**)&p_a, g_a);
    cudaGetSymbolAddress((void**)&p_b, g_b);
    cudaGetSymbolAddress((void**)&p_h, g_h);
    cudaGetSymbolAddress((void**)&p_qsum, g_qsum);
    cudaGetSymbolAddress((void**)&p_en, g_enorm);
    cudaGetSymbolAddress(&pv_resA, g_resA);
    cudaGetSymbolAddress(&pv_cbB, g_cbB);
    const __half* p_resA = (const __half*)pv_resA;
    const __half* p_cbB  = (const __half*)pv_cbB;

    // merged prep (2 launches instead of 6; value-identical)
    k_prep_all<<<4096, 256>>>(cbs, emb_std);
    k_prepW_all<<<1088, 256>>>(dec_w0, dec_w1, dec_g0, dec_w2, dec_g1);

    // encoder (fp32 — h must stay bit-compatible; enc0 fuses normalize via rstd)
    k_gemm<true, true><<<dim3(HD0 / 64, B_ / 64), 256>>>(x, enc_w0, enc_b0, p_a, HD0, DIN, emb_mean);
    k_rmsnorm<<<B_, 256>>>(p_a, enc_g0, HD0);
    k_gemm<true, false><<<dim3(HD1 / 64, B_ / 64), 256>>>(p_a, enc_w1, enc_b1, p_b, HD1, HD0, nullptr);
    k_rmsnorm<<<B_, 256>>>(p_b, enc_g1, HD1);
    k_gemm<true, false><<<dim3(HD2 / 64, B_ / 64), 256>>>(p_b, enc_w2, enc_b2, p_h, HD2, HD1, nullptr);
    k_rmsnorm_init<<<B_, 128>>>(enc_g2);

    // residual VQ (R11-proven)
    for (int q = 0; q < NQ; q++) {
        const float* cbq = cbs + (size_t)q * KC * HD2;
        k_vq_mma<<<256, 256, SMEM_VQ>>>(p_resA, p_cbB + (size_t)q * KC * 128,
                                        p_en + (size_t)q * KC);
        k_vq_finish<<<B_, 128>>>(cbq, p_en + (size_t)q * KC, out_ids, q,
                                 q == 0 ? 1 : 0);
    }

    // decoder (fp16 2-term; dec1/dec2 fuse the input rmsnorm via ssq + folded gain)
    k_gemm_h<true, false><<<dim3(HD1 / 64, B_ / 128), 256, SMEM_MLP>>>(
        p_qsum, dec_b0, p_b, HD1, HD2, WBASE0);
    k_gemm_h<true, true><<<dim3(HD0 / 64, B_ / 128), 256, SMEM_MLP>>>(
        p_b, dec_b1, p_a, HD0, HD1, WBASE1);
    k_gemm_h<false, true><<<dim3(DIN / 64, B_ / 128), 256, SMEM_MLP>>>(
        p_a, dec_b2, out_recon, DIN, HD0, WBASE2);

    // losses
    k_recon_part<<<2048, 256>>>(out_recon, x, emb_mean);
    k_vq_part<<<64, 256>>>();
    k_final<<<1, 256>>>(out_loss);
}